// round 2
// baseline (speedup 1.0000x reference)
#include <cuda_runtime.h>
#include <cuda_bf16.h>

#define Nb 8
#define LL 4096
#define SS 4096
#define EE 256
#define HH 8
#define DD 32
#define NTOK (Nb*LL)
#define EPSV 1e-6f
#define NCHUNK 8
#define CHS (SS/NCHUNK)

// ---------------- scratch (device globals; no dynamic alloc) ----------------
__device__ float g_Qf[NTOK*EE];        // feature-mapped Q  (32 MB)
__device__ float g_Kf[Nb*SS*EE];       // feature-mapped K  (32 MB)
__device__ float g_Vm[Nb*SS*EE];       // masked V / S      (32 MB)
__device__ float g_part[NCHUNK*Nb*HH*1056]; // partial KV+Ksum
__device__ float g_KV[Nb*HH*1056];     // [d*32+v] then Ksum at 1024+d
__device__ float g_UT[Nb*EE*EE];       // U^T[n][e'][h*32+d] = S*sum_v KV*Wm
__device__ float g_Z[NTOK*HH];         // normalizer per (row, h)
__device__ int   g_mask_kind;          // 0=u8 1=i32 2=f32 3=bf16

// ---------------- mask dtype detection ----------------
__global__ void detect_mask_kernel(const unsigned int* __restrict__ m, int nwords) {
    __shared__ int flags[3];
    if (threadIdx.x < 3) flags[threadIdx.x] = 0;
    __syncthreads();
    for (int i = threadIdx.x; i < nwords; i += blockDim.x) {
        unsigned w = m[i];
        if (w == 0x3F803F80u || w == 0x00003F80u) atomicOr(&flags[0], 1);      // bf16 evidence
        else if (w == 0x3F800000u) atomicOr(&flags[1], 1);                      // f32 (or bf16-hi)
        else if (w > 1u) {
            unsigned b0 = w & 255u, b1 = (w >> 8) & 255u, b2 = (w >> 16) & 255u, b3 = w >> 24;
            if (b0 <= 1u && b1 <= 1u && b2 <= 1u && b3 <= 1u) atomicOr(&flags[2], 1); // packed u8 bools
        }
    }
    __syncthreads();
    if (threadIdx.x == 0) {
        int kind;
        if (flags[0]) kind = 3;
        else if (flags[1]) kind = 2;
        else if (flags[2]) kind = 0;
        else kind = 1;
        g_mask_kind = kind;
    }
}

__device__ __forceinline__ float mask_val(const void* p, int i) {
    int k = g_mask_kind;
    if (k == 0) return ((const unsigned char*)p)[i] ? 1.f : 0.f;
    if (k == 1) return ((const int*)p)[i] ? 1.f : 0.f;
    if (k == 2) return ((const float*)p)[i];
    return __bfloat162float(((const __nv_bfloat16*)p)[i]);
}

// ---------------- tiled GEMM: C[M,N] = A[M,K] @ B[N,K]^T (+ epilogue) ----------------
#define BM 64
#define BN 64
#define BK 16
#define EPI_PLAIN 0
#define EPI_FEAT  1   // elu(x+b)+1, * mask[row]
#define EPI_VPROJ 2   // (x+b) * mask[row] * scale

__global__ __launch_bounds__(256) void gemm_nt(
    const float* __restrict__ A, const float* __restrict__ B,
    const float* __restrict__ bias, float* __restrict__ C,
    int M, int N, int K, int epi,
    const void* __restrict__ mask, float scale,
    const float* __restrict__ zrow,        // if non-null: scale A[row,k] by zrow[row*8 + k/32]
    int bBatchStride, int rowsPerBatch)    // if stride!=0: B += (rowBase/rowsPerBatch)*stride
{
    __shared__ float As[BK][BM];
    __shared__ float Bs[BK][BN];
    int tid = threadIdx.x;
    int bm = blockIdx.y * BM;
    int bn = blockIdx.x * BN;
    if (bBatchStride) B += (size_t)(bm / rowsPerBatch) * bBatchStride;
    int tx = tid & 15, ty = tid >> 4;
    float acc[4][4] = {};
    int lr = tid >> 2;        // 0..63
    int lc = (tid & 3) * 4;   // 0,4,8,12

    for (int k0 = 0; k0 < K; k0 += BK) {
        float4 av = *(const float4*)&A[(size_t)(bm + lr) * K + k0 + lc];
        if (zrow) {
            float z = zrow[(bm + lr) * HH + (k0 >> 5)];
            av.x *= z; av.y *= z; av.z *= z; av.w *= z;
        }
        float4 bv = *(const float4*)&B[(size_t)(bn + lr) * K + k0 + lc];
        As[lc + 0][lr] = av.x; As[lc + 1][lr] = av.y;
        As[lc + 2][lr] = av.z; As[lc + 3][lr] = av.w;
        Bs[lc + 0][lr] = bv.x; Bs[lc + 1][lr] = bv.y;
        Bs[lc + 2][lr] = bv.z; Bs[lc + 3][lr] = bv.w;
        __syncthreads();
#pragma unroll
        for (int kk = 0; kk < BK; kk++) {
            float4 a4 = *(const float4*)&As[kk][ty * 4];
            float4 b4 = *(const float4*)&Bs[kk][tx * 4];
            float ar[4] = {a4.x, a4.y, a4.z, a4.w};
            float br[4] = {b4.x, b4.y, b4.z, b4.w};
#pragma unroll
            for (int i = 0; i < 4; i++)
#pragma unroll
                for (int j = 0; j < 4; j++)
                    acc[i][j] += ar[i] * br[j];
        }
        __syncthreads();
    }

#pragma unroll
    for (int i = 0; i < 4; i++) {
        int row = bm + ty * 4 + i;
        float mv = (epi == EPI_PLAIN) ? 1.f : mask_val(mask, row);
        float4 out;
        float* o = &out.x;
#pragma unroll
        for (int j = 0; j < 4; j++) {
            int col = bn + tx * 4 + j;
            float v = acc[i][j];
            if (epi == EPI_FEAT) {
                v += bias[col];
                v = v > 0.f ? v + 1.f : expf(v);
                v *= mv;
            } else if (epi == EPI_VPROJ) {
                v = (v + bias[col]) * mv * scale;
            }
            o[j] = v;
        }
        *(float4*)&C[(size_t)row * N + bn + tx * 4] = out;
    }
}

// ---------------- KV aggregation: partial sums over S chunks ----------------
__global__ __launch_bounds__(256) void kv_partial() {
    int nh = blockIdx.x;            // 0..63
    int n = nh >> 3, h = nh & 7;
    int chunk = blockIdx.y;         // 0..NCHUNK-1
    __shared__ float Ks[64][32];
    __shared__ float Vs[64][32];
    int tid = threadIdx.x;
    int d = tid >> 3;
    int vg = (tid & 7) * 4;
    float a0 = 0, a1 = 0, a2 = 0, a3 = 0, ks = 0;
    int s0base = chunk * CHS;
    const float* Kp = g_Kf + (size_t)n * SS * EE + h * DD;
    const float* Vp = g_Vm + (size_t)n * SS * EE + h * DD;
    for (int s0 = 0; s0 < CHS; s0 += 64) {
#pragma unroll
        for (int r = 0; r < 2; r++) {
            int idx = tid + r * 256;
            int row = idx >> 3, c = (idx & 7) * 4;
            size_t g = (size_t)(s0base + s0 + row) * EE + c;
            *(float4*)&Ks[row][c] = *(const float4*)&Kp[g];
            *(float4*)&Vs[row][c] = *(const float4*)&Vp[g];
        }
        __syncthreads();
#pragma unroll 8
        for (int s = 0; s < 64; s++) {
            float kf = Ks[s][d];
            float4 vv = *(const float4*)&Vs[s][vg];
            ks += kf;
            a0 += kf * vv.x; a1 += kf * vv.y; a2 += kf * vv.z; a3 += kf * vv.w;
        }
        __syncthreads();
    }
    float* P = g_part + ((size_t)chunk * 64 + nh) * 1056;
    P[d * 32 + vg + 0] = a0; P[d * 32 + vg + 1] = a1;
    P[d * 32 + vg + 2] = a2; P[d * 32 + vg + 3] = a3;
    if ((tid & 7) == 0) P[1024 + d] = ks;
}

__global__ void kv_reduce() {
    int nh = blockIdx.x;
    for (int i = threadIdx.x; i < 1056; i += blockDim.x) {
        float s = 0;
        for (int c = 0; c < NCHUNK; c++) s += g_part[((size_t)c * 64 + nh) * 1056 + i];
        g_KV[(size_t)nh * 1056 + i] = s;
    }
}

// ---------------- U^T[n][e'][h*32+d] = S * sum_v KV[n,h,d,v] * Wm[e', h*32+v] ----------------
__global__ __launch_bounds__(256) void make_ut(const float* __restrict__ Wm) {
    int nh = blockIdx.x; int n = nh >> 3, h = nh & 7;
    __shared__ float KVs[32][32];
    int tid = threadIdx.x;
    for (int i = tid; i < 1024; i += 256) KVs[i >> 5][i & 31] = g_KV[(size_t)nh * 1056 + i];
    __syncthreads();
    int ep = tid;  // e' in 0..255
    float w[32];
#pragma unroll
    for (int v = 0; v < 32; v++) w[v] = Wm[(size_t)ep * EE + h * DD + v];
    float* out = g_UT + ((size_t)n * EE + ep) * EE + h * DD;
#pragma unroll
    for (int d2 = 0; d2 < 32; d2++) {
        float a = 0;
#pragma unroll
        for (int v = 0; v < 32; v++) a += KVs[d2][v] * w[v];
        out[d2] = a * (float)SS;
    }
}

// ---------------- Z[row,h] = 1 / (Qf[row,h,:] . Ksum[n,h,:] + eps) ----------------
__global__ void z_kernel() {
    int t = blockIdx.x * blockDim.x + threadIdx.x;   // t = row*8 + h
    int row = t >> 3, h = t & 7;
    int n = row / LL;
    const float* q = g_Qf + (size_t)row * EE + h * DD;
    const float* ks = g_KV + (size_t)(n * HH + h) * 1056 + 1024;
    float a = 0;
#pragma unroll
    for (int d2 = 0; d2 < 32; d2++) a += q[d2] * ks[d2];
    g_Z[t] = 1.f / (a + EPSV);
}

// ---------------- launch ----------------
extern "C" void kernel_launch(void* const* d_in, const int* in_sizes, int n_in,
                              void* d_out, int out_size) {
    const float* q  = (const float*)d_in[0];
    const float* k  = (const float*)d_in[1];
    const float* v  = (const float*)d_in[2];
    const void*  qm = d_in[3];
    const void*  km = d_in[4];
    const float* Wq = (const float*)d_in[5];
    const float* bq = (const float*)d_in[6];
    const float* Wk = (const float*)d_in[7];
    const float* bk = (const float*)d_in[8];
    const float* Wv = (const float*)d_in[9];
    const float* bv = (const float*)d_in[10];
    const float* Wm = (const float*)d_in[11];
    float* out = (float*)d_out;

    float *Qf, *Kf, *Vm, *UT, *Z;
    cudaGetSymbolAddress((void**)&Qf, g_Qf);
    cudaGetSymbolAddress((void**)&Kf, g_Kf);
    cudaGetSymbolAddress((void**)&Vm, g_Vm);
    cudaGetSymbolAddress((void**)&UT, g_UT);
    cudaGetSymbolAddress((void**)&Z,  g_Z);

    detect_mask_kernel<<<1, 256>>>((const unsigned int*)km, 2048);

    dim3 gr(EE / BN, NTOK / BM);  // (4, 512)
    gemm_nt<<<gr, 256>>>(q, Wq, bq, Qf, NTOK, EE, EE, EPI_FEAT, qm, 1.f, nullptr, 0, 0);
    gemm_nt<<<gr, 256>>>(k, Wk, bk, Kf, NTOK, EE, EE, EPI_FEAT, km, 1.f, nullptr, 0, 0);
    gemm_nt<<<gr, 256>>>(v, Wv, bv, Vm, NTOK, EE, EE, EPI_VPROJ, km, 1.f / (float)SS, nullptr, 0, 0);

    kv_partial<<<dim3(64, NCHUNK), 256>>>();
    kv_reduce<<<64, 256>>>();
    make_ut<<<64, 256>>>(Wm);
    z_kernel<<<(NTOK * HH) / 256, 256>>>();

    // final = (Qf * Z) @ U[n]^T  — fuses normalizer, *S, Qf@KV and merge proj
    gemm_nt<<<gr, 256>>>(Qf, UT, nullptr, out, NTOK, EE, EE, EPI_PLAIN, nullptr, 1.f, Z, EE * EE, LL);
}

// round 4
// speedup vs baseline: 2.0825x; 2.0825x over previous
#include <cuda_runtime.h>
#include <cuda_bf16.h>
#include <cstdint>

#define Nb 8
#define LL 4096
#define SS 4096
#define EE 256
#define HH 8
#define DD 32
#define NTOK (Nb*LL)
#define EPSV 1e-6f
#define NCHUNK 8
#define CHS (SS/NCHUNK)

// ---------------- scratch (device globals; no dynamic alloc) ----------------
__device__ float g_Qf[NTOK*EE];        // feature-mapped Q  (32 MB)
__device__ float g_Kf[Nb*SS*EE];       // feature-mapped K  (32 MB)
__device__ float g_Vm[Nb*SS*EE];       // masked V / S      (32 MB)
__device__ float g_part[NCHUNK*Nb*HH*1056]; // partial KV+Ksum
__device__ float g_KV[Nb*HH*1056];     // [d*32+v] then Ksum at 1024+d
__device__ float g_UT[Nb*EE*EE];       // U^T[n][e'][h*32+d]
__device__ float g_Z[NTOK*HH];         // normalizer per (row, h)
__device__ int   g_mask_kind;          // 0=u8 1=i32 2=f32 3=bf16

// ---------------- helpers ----------------
__device__ __forceinline__ uint32_t smem_u32(const void* p) {
    uint32_t a;
    asm("{ .reg .u64 t; cvta.to.shared.u64 t, %1; cvt.u32.u64 %0, t; }" : "=r"(a) : "l"(p));
    return a;
}
__device__ __forceinline__ void ldsm4(unsigned* r, uint32_t addr) {
    asm volatile("ldmatrix.sync.aligned.m8n8.x4.shared.b16 {%0,%1,%2,%3}, [%4];"
        : "=r"(r[0]), "=r"(r[1]), "=r"(r[2]), "=r"(r[3]) : "r"(addr));
}
__device__ __forceinline__ void mma16816(float* c, const unsigned* a, const unsigned* b) {
    asm volatile("mma.sync.aligned.m16n8k16.row.col.f32.bf16.bf16.f32 "
        "{%0,%1,%2,%3}, {%4,%5,%6,%7}, {%8,%9}, {%0,%1,%2,%3};"
        : "+f"(c[0]), "+f"(c[1]), "+f"(c[2]), "+f"(c[3])
        : "r"(a[0]), "r"(a[1]), "r"(a[2]), "r"(a[3]), "r"(b[0]), "r"(b[1]));
}
// split fp32 pair -> (hi bf16x2, lo bf16x2)
__device__ __forceinline__ uint2 splitpack(float x0, float x1) {
    __nv_bfloat162 h = __float22bfloat162_rn(make_float2(x0, x1));
    float2 hf = __bfloat1622float2(h);
    __nv_bfloat162 l = __float22bfloat162_rn(make_float2(x0 - hf.x, x1 - hf.y));
    uint2 o;
    o.x = *(unsigned*)&h;
    o.y = *(unsigned*)&l;
    return o;
}

// ---------------- mask dtype detection ----------------
__global__ void detect_mask_kernel(const unsigned int* __restrict__ m, int nwords) {
    __shared__ int flags[3];
    if (threadIdx.x < 3) flags[threadIdx.x] = 0;
    __syncthreads();
    for (int i = threadIdx.x; i < nwords; i += blockDim.x) {
        unsigned w = m[i];
        if (w == 0x3F803F80u || w == 0x00003F80u) atomicOr(&flags[0], 1);
        else if (w == 0x3F800000u) atomicOr(&flags[1], 1);
        else if (w > 1u) {
            unsigned b0 = w & 255u, b1 = (w >> 8) & 255u, b2 = (w >> 16) & 255u, b3 = w >> 24;
            if (b0 <= 1u && b1 <= 1u && b2 <= 1u && b3 <= 1u) atomicOr(&flags[2], 1);
        }
    }
    __syncthreads();
    if (threadIdx.x == 0) {
        int kind;
        if (flags[0]) kind = 3;
        else if (flags[1]) kind = 2;
        else if (flags[2]) kind = 0;
        else kind = 1;
        g_mask_kind = kind;
    }
}

__device__ __forceinline__ float mask_val(const void* p, int i) {
    int k = g_mask_kind;
    if (k == 0) return ((const unsigned char*)p)[i] ? 1.f : 0.f;
    if (k == 1) return ((const int*)p)[i] ? 1.f : 0.f;
    if (k == 2) return ((const float*)p)[i];
    return __bfloat162float(((const __nv_bfloat16*)p)[i]);
}

// ================= mma.sync split-bf16 GEMM: C[M,256] = A[M,256] @ B[256,256]^T =================
#define EPI_PLAIN 0
#define EPI_FEAT  1
#define EPI_VPROJ 2
#define PITCHB 144            // smem row pitch in bytes (72 bf16) -> conflict-free ldmatrix
#define TILEB (128*PITCHB)    // 18432 B per tile array

extern __shared__ char dyn_smem[];

__global__ void __launch_bounds__(256, 2) tgemm(
    const float* __restrict__ A, const float* __restrict__ B,
    const float* __restrict__ bias, float* __restrict__ C,
    int epi, const void* __restrict__ mask, float scale,
    const float* __restrict__ zrow, int bBatchStride)
{
    char* smAh = dyn_smem;
    char* smAl = dyn_smem + TILEB;
    char* smBh = dyn_smem + 2 * TILEB;
    char* smBl = dyn_smem + 3 * TILEB;
    uint32_t AhU = smem_u32(smAh), AlU = smem_u32(smAl);
    uint32_t BhU = smem_u32(smBh), BlU = smem_u32(smBl);

    int tid = threadIdx.x, wid = tid >> 5, lane = tid & 31;
    int wm = wid >> 2, wn = wid & 3;                  // warp grid 2 x 4
    int bm = blockIdx.y * 128, bn = blockIdx.x * 128;
    if (bBatchStride) B += (size_t)(bm / LL) * bBatchStride;

    int lmat = lane >> 3, lrow = lane & 7;
    // ldmatrix x4 address components (in bytes), per thread
    // A: mats 0:(rb,cb) 1:(rb+8,cb) 2:(rb,cb+8) 3:(rb+8,cb+8)   [rows=m, cols=k halves]
    int a_roff = ((lmat & 1) ? 8 : 0) + lrow;
    int a_coff = (lmat & 2) ? 16 : 0;                 // bytes (8 halves)
    // B: mats 0:(nb,cb) 1:(nb,cb+8) 2:(nb+8,cb) 3:(nb+8,cb+8)   [rows=n, cols=k halves]
    int b_roff = ((lmat & 2) ? 8 : 0) + lrow;
    int b_coff = (lmat & 1) ? 16 : 0;

    float acc[4][4][4];
#pragma unroll
    for (int mi = 0; mi < 4; mi++)
#pragma unroll
        for (int ni = 0; ni < 4; ni++)
#pragma unroll
            for (int j = 0; j < 4; j++) acc[mi][ni][j] = 0.f;

    for (int kc = 0; kc < 4; kc++) {
        __syncthreads();
        // ---- fill: load fp32 tiles, split into hi/lo bf16 ----
#pragma unroll
        for (int i = 0; i < 8; i++) {
            int idx = tid + i * 256;                  // 0..2047 float4 groups
            int r = idx >> 4, c4 = (idx & 15) << 2;   // row, float col
            int off = r * PITCHB + c4 * 2;
            float4 av = *(const float4*)&A[(size_t)(bm + r) * EE + kc * 64 + c4];
            if (zrow) {
                float z = zrow[(bm + r) * HH + ((kc * 64 + c4) >> 5)];
                av.x *= z; av.y *= z; av.z *= z; av.w *= z;
            }
            uint2 s0 = splitpack(av.x, av.y);
            uint2 s1 = splitpack(av.z, av.w);
            *(uint2*)(smAh + off) = make_uint2(s0.x, s1.x);
            *(uint2*)(smAl + off) = make_uint2(s0.y, s1.y);
            float4 bv = *(const float4*)&B[(size_t)(bn + r) * EE + kc * 64 + c4];
            uint2 t0 = splitpack(bv.x, bv.y);
            uint2 t1 = splitpack(bv.z, bv.w);
            *(uint2*)(smBh + off) = make_uint2(t0.x, t1.x);
            *(uint2*)(smBl + off) = make_uint2(t0.y, t1.y);
        }
        __syncthreads();
        // ---- compute: 4 k16-steps, 3 split terms each ----
#pragma unroll
        for (int ks = 0; ks < 4; ks++) {
            int cbb = ks * 32;                        // k col offset in bytes
            unsigned ah[4][4], bh[4][2], bx[4][2], tmp[4];
            // A-hi frags
#pragma unroll
            for (int mi = 0; mi < 4; mi++) {
                int rb = wm * 64 + mi * 16;
                ldsm4(ah[mi], AhU + (rb + a_roff) * PITCHB + cbb + a_coff);
            }
            // B-hi frags
#pragma unroll
            for (int p = 0; p < 2; p++) {
                int nb = wn * 32 + p * 16;
                ldsm4(tmp, BhU + (nb + b_roff) * PITCHB + cbb + b_coff);
                bh[2*p][0] = tmp[0]; bh[2*p][1] = tmp[1];
                bh[2*p+1][0] = tmp[2]; bh[2*p+1][1] = tmp[3];
            }
#pragma unroll
            for (int mi = 0; mi < 4; mi++)
#pragma unroll
                for (int ni = 0; ni < 4; ni++) mma16816(acc[mi][ni], ah[mi], bh[ni]);
            // B-lo frags: Ah*Bl
#pragma unroll
            for (int p = 0; p < 2; p++) {
                int nb = wn * 32 + p * 16;
                ldsm4(tmp, BlU + (nb + b_roff) * PITCHB + cbb + b_coff);
                bx[2*p][0] = tmp[0]; bx[2*p][1] = tmp[1];
                bx[2*p+1][0] = tmp[2]; bx[2*p+1][1] = tmp[3];
            }
#pragma unroll
            for (int mi = 0; mi < 4; mi++)
#pragma unroll
                for (int ni = 0; ni < 4; ni++) mma16816(acc[mi][ni], ah[mi], bx[ni]);
            // A-lo frags (reuse ah regs): Al*Bh
#pragma unroll
            for (int mi = 0; mi < 4; mi++) {
                int rb = wm * 64 + mi * 16;
                ldsm4(ah[mi], AlU + (rb + a_roff) * PITCHB + cbb + a_coff);
            }
#pragma unroll
            for (int mi = 0; mi < 4; mi++)
#pragma unroll
                for (int ni = 0; ni < 4; ni++) mma16816(acc[mi][ni], ah[mi], bh[ni]);
        }
    }

    // ---- epilogue ----
    int g = lane >> 2, tc = lane & 3;
#pragma unroll
    for (int mi = 0; mi < 4; mi++) {
        int r0 = bm + wm * 64 + mi * 16 + g;
        int r1 = r0 + 8;
        float mv0 = 1.f, mv1 = 1.f;
        if (epi != EPI_PLAIN) { mv0 = mask_val(mask, r0); mv1 = mask_val(mask, r1); }
#pragma unroll
        for (int ni = 0; ni < 4; ni++) {
            int col = bn + wn * 32 + ni * 8 + tc * 2;
            float c0 = acc[mi][ni][0], c1 = acc[mi][ni][1];
            float c2 = acc[mi][ni][2], c3 = acc[mi][ni][3];
            if (epi == EPI_FEAT) {
                float b0 = bias[col], b1 = bias[col + 1];
                c0 += b0; c1 += b1; c2 += b0; c3 += b1;
                c0 = c0 > 0.f ? c0 + 1.f : expf(c0);
                c1 = c1 > 0.f ? c1 + 1.f : expf(c1);
                c2 = c2 > 0.f ? c2 + 1.f : expf(c2);
                c3 = c3 > 0.f ? c3 + 1.f : expf(c3);
                c0 *= mv0; c1 *= mv0; c2 *= mv1; c3 *= mv1;
            } else if (epi == EPI_VPROJ) {
                float b0 = bias[col], b1 = bias[col + 1];
                c0 = (c0 + b0) * mv0 * scale; c1 = (c1 + b1) * mv0 * scale;
                c2 = (c2 + b0) * mv1 * scale; c3 = (c3 + b1) * mv1 * scale;
            }
            *(float2*)&C[(size_t)r0 * EE + col] = make_float2(c0, c1);
            *(float2*)&C[(size_t)r1 * EE + col] = make_float2(c2, c3);
        }
    }
}

// ---------------- KV aggregation: partial sums over S chunks ----------------
__global__ __launch_bounds__(256) void kv_partial() {
    int nh = blockIdx.x;
    int n = nh >> 3, h = nh & 7;
    int chunk = blockIdx.y;
    __shared__ float Ks[64][32];
    __shared__ float Vs[64][32];
    int tid = threadIdx.x;
    int d = tid >> 3;
    int vg = (tid & 7) * 4;
    float a0 = 0, a1 = 0, a2 = 0, a3 = 0, ks = 0;
    int s0base = chunk * CHS;
    const float* Kp = g_Kf + (size_t)n * SS * EE + h * DD;
    const float* Vp = g_Vm + (size_t)n * SS * EE + h * DD;
    for (int s0 = 0; s0 < CHS; s0 += 64) {
#pragma unroll
        for (int r = 0; r < 2; r++) {
            int idx = tid + r * 256;
            int row = idx >> 3, c = (idx & 7) * 4;
            size_t gidx = (size_t)(s0base + s0 + row) * EE + c;
            *(float4*)&Ks[row][c] = *(const float4*)&Kp[gidx];
            *(float4*)&Vs[row][c] = *(const float4*)&Vp[gidx];
        }
        __syncthreads();
#pragma unroll 8
        for (int s = 0; s < 64; s++) {
            float kf = Ks[s][d];
            float4 vv = *(const float4*)&Vs[s][vg];
            ks += kf;
            a0 += kf * vv.x; a1 += kf * vv.y; a2 += kf * vv.z; a3 += kf * vv.w;
        }
        __syncthreads();
    }
    float* P = g_part + ((size_t)chunk * 64 + nh) * 1056;
    P[d * 32 + vg + 0] = a0; P[d * 32 + vg + 1] = a1;
    P[d * 32 + vg + 2] = a2; P[d * 32 + vg + 3] = a3;
    if ((tid & 7) == 0) P[1024 + d] = ks;
}

__global__ void kv_reduce() {
    int nh = blockIdx.x;
    for (int i = threadIdx.x; i < 1056; i += blockDim.x) {
        float s = 0;
        for (int c = 0; c < NCHUNK; c++) s += g_part[((size_t)c * 64 + nh) * 1056 + i];
        g_KV[(size_t)nh * 1056 + i] = s;
    }
}

__global__ __launch_bounds__(256) void make_ut(const float* __restrict__ Wm) {
    int nh = blockIdx.x; int n = nh >> 3, h = nh & 7;
    __shared__ float KVs[32][32];
    int tid = threadIdx.x;
    for (int i = tid; i < 1024; i += 256) KVs[i >> 5][i & 31] = g_KV[(size_t)nh * 1056 + i];
    __syncthreads();
    int ep = tid;
    float w[32];
#pragma unroll
    for (int v = 0; v < 32; v++) w[v] = Wm[(size_t)ep * EE + h * DD + v];
    float* out = g_UT + ((size_t)n * EE + ep) * EE + h * DD;
#pragma unroll
    for (int d2 = 0; d2 < 32; d2++) {
        float a = 0;
#pragma unroll
        for (int v = 0; v < 32; v++) a += KVs[d2][v] * w[v];
        out[d2] = a * (float)SS;
    }
}

__global__ void z_kernel() {
    int t = blockIdx.x * blockDim.x + threadIdx.x;
    int row = t >> 3, h = t & 7;
    int n = row / LL;
    const float* q = g_Qf + (size_t)row * EE + h * DD;
    const float* ks = g_KV + (size_t)(n * HH + h) * 1056 + 1024;
    float a = 0;
#pragma unroll
    for (int d2 = 0; d2 < 32; d2++) a += q[d2] * ks[d2];
    g_Z[t] = 1.f / (a + EPSV);
}

// ---------------- launch ----------------
extern "C" void kernel_launch(void* const* d_in, const int* in_sizes, int n_in,
                              void* d_out, int out_size) {
    const float* q  = (const float*)d_in[0];
    const float* k  = (const float*)d_in[1];
    const float* v  = (const float*)d_in[2];
    const void*  qm = d_in[3];
    const void*  km = d_in[4];
    const float* Wq = (const float*)d_in[5];
    const float* bq = (const float*)d_in[6];
    const float* Wk = (const float*)d_in[7];
    const float* bk = (const float*)d_in[8];
    const float* Wv = (const float*)d_in[9];
    const float* bv = (const float*)d_in[10];
    const float* Wm = (const float*)d_in[11];
    float* out = (float*)d_out;

    float *Qf, *Kf, *Vm, *UT, *Z;
    cudaGetSymbolAddress((void**)&Qf, g_Qf);
    cudaGetSymbolAddress((void**)&Kf, g_Kf);
    cudaGetSymbolAddress((void**)&Vm, g_Vm);
    cudaGetSymbolAddress((void**)&UT, g_UT);
    cudaGetSymbolAddress((void**)&Z,  g_Z);

    const int SMEM_SZ = 4 * TILEB;  // 73728 B
    cudaFuncSetAttribute(tgemm, cudaFuncAttributeMaxDynamicSharedMemorySize, SMEM_SZ);

    detect_mask_kernel<<<1, 256>>>((const unsigned int*)km, 2048);

    dim3 gr(2, NTOK / 128);  // (2, 256)
    tgemm<<<gr, 256, SMEM_SZ>>>(q, Wq, bq, Qf, EPI_FEAT, qm, 1.f, nullptr, 0);
    tgemm<<<gr, 256, SMEM_SZ>>>(k, Wk, bk, Kf, EPI_FEAT, km, 1.f, nullptr, 0);
    tgemm<<<gr, 256, SMEM_SZ>>>(v, Wv, bv, Vm, EPI_VPROJ, km, 1.f / (float)SS, nullptr, 0);

    kv_partial<<<dim3(64, NCHUNK), 256>>>();
    kv_reduce<<<64, 256>>>();
    make_ut<<<64, 256>>>(Wm);
    z_kernel<<<(NTOK * HH) / 256, 256>>>();

    tgemm<<<gr, 256, SMEM_SZ>>>(Qf, UT, nullptr, out, EPI_PLAIN, nullptr, 1.f, Z, EE * EE);
}